// round 4
// baseline (speedup 1.0000x reference)
#include <cuda_runtime.h>
#include <cuda_bf16.h>

#define NN 50000
#define NE 600000
#define NG 64

// ---- scratch (device globals; no runtime allocation allowed) ----
__device__ float g_dinv[NN];
__device__ int   g_deg[NN];
__device__ int   g_cur[NN];
__device__ int   g_rowptr[NN + 1];
__device__ int   g_src[NE];
__device__ float g_nrm[NE];
__device__ __align__(16) float g_h[NN * 128];
__device__ __align__(16) float g_agg[NN * 128];
__device__ float g_pool[NG * 64];
__device__ float g_cnt[NG];

// ---------------- CSR build ----------------
__global__ void k_zero_deg() {
    int i = blockIdx.x * blockDim.x + threadIdx.x;
    if (i < NN) g_deg[i] = 0;
}

__global__ void k_deg_count(const int* __restrict__ ei) {
    int e = blockIdx.x * blockDim.x + threadIdx.x;
    if (e < NE) atomicAdd(&g_deg[ei[NE + e]], 1);
}

// single block exclusive scan over 50000 degrees; also dinv + cursor reset
__global__ void k_scan() {
    __shared__ int sh[1024];
    __shared__ int sbase;
    int tid = threadIdx.x;
    if (tid == 0) { sbase = 0; g_rowptr[0] = 0; }
    __syncthreads();
    for (int start = 0; start < NN; start += 1024) {
        int i = start + tid;
        int v = (i < NN) ? g_deg[i] : 0;
        if (i < NN) {
            g_dinv[i] = rsqrtf((float)v + 1.0f);  // +1 self-loop
            g_cur[i] = 0;
        }
        sh[tid] = v;
        __syncthreads();
        for (int off = 1; off < 1024; off <<= 1) {
            int t = (tid >= off) ? sh[tid - off] : 0;
            __syncthreads();
            sh[tid] += t;
            __syncthreads();
        }
        if (i < NN) g_rowptr[i + 1] = sbase + sh[tid];
        __syncthreads();
        if (tid == 0) sbase += sh[1023];
        __syncthreads();
    }
}

__global__ void k_fill(const int* __restrict__ ei) {
    int e = blockIdx.x * blockDim.x + threadIdx.x;
    if (e >= NE) return;
    int r = ei[e];
    int c = ei[NE + e];
    int slot = g_rowptr[c] + atomicAdd(&g_cur[c], 1);
    g_src[slot] = r;
    g_nrm[slot] = g_dinv[r] * g_dinv[c];
}

// ---------------- GEMM: C[M,BN] = reluOpt(A) @ W ----------------
// BM=128, BK=8, 256 threads, per-thread 8 x TN
template <int BN, int TN, bool RELU>
__global__ void k_gemm(const float* __restrict__ A, const float* __restrict__ W,
                       float* __restrict__ C, int M, int K) {
    constexpr int BM = 128, BK = 8, TM = 8;
    __shared__ float As[BK][BM];
    __shared__ float Ws[BK][BN];

    int tid = threadIdx.x;
    int block_row = blockIdx.x * BM;
    constexpr int CG = BN / TN;           // column groups
    int tcol = (tid % CG) * TN;
    int trow = (tid / CG) * TM;

    float acc[TM][TN] = {};

    for (int k0 = 0; k0 < K; k0 += BK) {
        // A tile: 128 rows x 8 k (256 float4 loads, transpose into As[k][m])
        {
            int m = tid >> 1, seg = tid & 1;
            int gm = block_row + m;
            float4 v = make_float4(0.f, 0.f, 0.f, 0.f);
            if (gm < M) v = *(const float4*)(A + (size_t)gm * K + k0 + seg * 4);
            if (RELU) {
                v.x = fmaxf(v.x, 0.f); v.y = fmaxf(v.y, 0.f);
                v.z = fmaxf(v.z, 0.f); v.w = fmaxf(v.w, 0.f);
            }
            As[seg * 4 + 0][m] = v.x;
            As[seg * 4 + 1][m] = v.y;
            As[seg * 4 + 2][m] = v.z;
            As[seg * 4 + 3][m] = v.w;
        }
        // W tile: 8 x BN
        constexpr int WLD = BK * BN / 4;
        if (tid < WLD) {
            int kk = tid / (BN / 4);
            int nn = (tid % (BN / 4)) * 4;
            *(float4*)&Ws[kk][nn] = *(const float4*)(W + (size_t)(k0 + kk) * BN + nn);
        }
        __syncthreads();

#pragma unroll
        for (int kk = 0; kk < BK; kk++) {
            float a[TM], w[TN];
#pragma unroll
            for (int i = 0; i < TM; i++) a[i] = As[kk][trow + i];
#pragma unroll
            for (int j = 0; j < TN; j += 4) *(float4*)&w[j] = *(float4*)&Ws[kk][tcol + j];
#pragma unroll
            for (int i = 0; i < TM; i++)
#pragma unroll
                for (int j = 0; j < TN; j++) acc[i][j] = fmaf(a[i], w[j], acc[i][j]);
        }
        __syncthreads();
    }

#pragma unroll
    for (int i = 0; i < TM; i++) {
        int gm = block_row + trow + i;
        if (gm < M) {
#pragma unroll
            for (int j = 0; j < TN; j += 4)
                *(float4*)(C + (size_t)gm * BN + tcol + j) = *(float4*)&acc[i][j];
        }
    }
}

// ---------------- gather aggregation: warp per target node ----------------
template <int F>
__global__ void k_gather(const float* __restrict__ b) {
    int warp = (blockIdx.x * blockDim.x + threadIdx.x) >> 5;
    int lane = threadIdx.x & 31;
    if (warp >= NN) return;
    int c = warp;
    float d = g_dinv[c];
    float dd = d * d;

    if (F == 128) {
        float4 v = *((const float4*)(g_h + (size_t)c * 128) + lane);
        float4 bb = *((const float4*)b + lane);
        float4 acc = make_float4(bb.x + dd * v.x, bb.y + dd * v.y,
                                 bb.z + dd * v.z, bb.w + dd * v.w);
        int s0 = g_rowptr[c], s1 = g_rowptr[c + 1];
        for (int j = s0; j < s1; j++) {
            int s = g_src[j];
            float w = g_nrm[j];
            float4 hv = *((const float4*)(g_h + (size_t)s * 128) + lane);
            acc.x = fmaf(w, hv.x, acc.x);
            acc.y = fmaf(w, hv.y, acc.y);
            acc.z = fmaf(w, hv.z, acc.z);
            acc.w = fmaf(w, hv.w, acc.w);
        }
        *((float4*)(g_agg + (size_t)c * 128) + lane) = acc;
    } else {  // F == 64
        float2 v = *((const float2*)(g_h + (size_t)c * 64) + lane);
        float2 bb = *((const float2*)b + lane);
        float2 acc = make_float2(bb.x + dd * v.x, bb.y + dd * v.y);
        int s0 = g_rowptr[c], s1 = g_rowptr[c + 1];
        for (int j = s0; j < s1; j++) {
            int s = g_src[j];
            float w = g_nrm[j];
            float2 hv = *((const float2*)(g_h + (size_t)s * 64) + lane);
            acc.x = fmaf(w, hv.x, acc.x);
            acc.y = fmaf(w, hv.y, acc.y);
        }
        *((float2*)(g_agg + (size_t)c * 64) + lane) = acc;
    }
}

// ---------------- pooling ----------------
__global__ void k_zero_pool() {
    int i = blockIdx.x * blockDim.x + threadIdx.x;
    if (i < NG * 64) g_pool[i] = 0.f;
}

// counts via binary search on sorted batch
__global__ void k_cnt(const int* __restrict__ batch) {
    int g = threadIdx.x;
    if (g >= NG) return;
    int lo = 0, hi = NN;
    while (lo < hi) { int mid = (lo + hi) >> 1; if (batch[mid] < g) lo = mid + 1; else hi = mid; }
    int a = lo;
    lo = 0; hi = NN;
    while (lo < hi) { int mid = (lo + hi) >> 1; if (batch[mid] < g + 1) lo = mid + 1; else hi = mid; }
    g_cnt[g] = (float)(lo - a);
}

// blockDim (64,4): x=feature, y=node sub-stride; run-length accumulate (batch sorted)
__global__ void k_pool(const int* __restrict__ batch) {
    int f = threadIdx.x;
    int sub = threadIdx.y;
    int chunk = (NN + gridDim.x - 1) / gridDim.x;
    int start = blockIdx.x * chunk;
    int end = min(NN, start + chunk);
    float acc = 0.f;
    int cur = -1;
    for (int i = start + sub; i < end; i += 4) {
        int g = batch[i];
        if (g != cur) {
            if (cur >= 0) atomicAdd(&g_pool[cur * 64 + f], acc);
            cur = g;
            acc = 0.f;
        }
        acc += fmaxf(g_agg[(size_t)i * 64 + f], 0.f);  // relu(h3)
    }
    if (cur >= 0) atomicAdd(&g_pool[cur * 64 + f], acc);
}

// ---------------- FC head ----------------
__global__ void k_fc(const float* __restrict__ Wf1, const float* __restrict__ bf1,
                     const float* __restrict__ Wf2, const float* __restrict__ bf2,
                     float* __restrict__ out) {
    __shared__ float sp[NG * 64];
    __shared__ float sf[NG * 32];
    int tid = threadIdx.x;
    for (int idx = tid; idx < NG * 64; idx += blockDim.x)
        sp[idx] = g_pool[idx] / fmaxf(g_cnt[idx >> 6], 1.0f);
    __syncthreads();
    for (int e = tid; e < NG * 32; e += blockDim.x) {
        int g = e / 32, j = e % 32;
        float s = bf1[j];
#pragma unroll
        for (int k = 0; k < 64; k++) s = fmaf(sp[g * 64 + k], Wf1[k * 32 + j], s);
        sf[e] = fmaxf(s, 0.f);
    }
    __syncthreads();
    for (int e = tid; e < NG * 10; e += blockDim.x) {
        int g = e / 10, j = e % 10;
        float s = bf2[j];
#pragma unroll
        for (int k = 0; k < 32; k++) s = fmaf(sf[g * 32 + k], Wf2[k * 10 + j], s);
        out[e] = s;
    }
}

// ---------------- launch ----------------
extern "C" void kernel_launch(void* const* d_in, const int* in_sizes, int n_in,
                              void* d_out, int out_size) {
    const float* x = (const float*)d_in[0];
    const int* ei = (const int*)d_in[1];       // int32 (JAX x64 disabled)
    const int* batch = (const int*)d_in[2];    // int32
    const float* W1 = (const float*)d_in[3];
    const float* b1 = (const float*)d_in[4];
    const float* W2 = (const float*)d_in[5];
    const float* b2 = (const float*)d_in[6];
    const float* W3 = (const float*)d_in[7];
    const float* b3 = (const float*)d_in[8];
    const float* Wf1 = (const float*)d_in[9];
    const float* bf1 = (const float*)d_in[10];
    const float* Wf2 = (const float*)d_in[11];
    const float* bf2 = (const float*)d_in[12];
    float* out = (float*)d_out;

    // Resolve device-global addresses (host-side symbol decay is invalid).
    float *p_h = nullptr, *p_agg = nullptr;
    cudaGetSymbolAddress((void**)&p_h, g_h);
    cudaGetSymbolAddress((void**)&p_agg, g_agg);

    const int T = 256;
    int gN = (NN + T - 1) / T;
    int gE = (NE + T - 1) / T;
    int gGemm = (NN + 127) / 128;
    int gGather = (NN * 32 + T - 1) / T;

    // CSR build
    k_zero_deg<<<gN, T>>>();
    k_deg_count<<<gE, T>>>(ei);
    k_scan<<<1, 1024>>>();
    k_fill<<<gE, T>>>(ei);

    // layer 1
    k_gemm<128, 8, false><<<gGemm, T>>>(x, W1, p_h, NN, 128);
    k_gather<128><<<gGather, T>>>(b1);
    // layer 2
    k_gemm<128, 8, true><<<gGemm, T>>>(p_agg, W2, p_h, NN, 128);
    k_gather<128><<<gGather, T>>>(b2);
    // layer 3
    k_gemm<64, 4, true><<<gGemm, T>>>(p_agg, W3, p_h, NN, 128);
    k_gather<64><<<gGather, T>>>(b3);

    // pool + head
    k_zero_pool<<<(NG * 64 + T - 1) / T, T>>>();
    k_cnt<<<1, 64>>>(batch);
    dim3 pb(64, 4);
    k_pool<<<128, pb>>>(batch);
    k_fc<<<1, 256>>>(Wf1, bf1, Wf2, bf2, out);
}

// round 5
// speedup vs baseline: 1.2382x; 1.2382x over previous
#include <cuda_runtime.h>
#include <cuda_bf16.h>

#define NN 50000
#define NE 600000
#define NG 64

// ---- scratch (device globals) ----
__device__ float g_dinv[NN];
__device__ int   g_deg[NN];
__device__ int   g_cur[NN];
__device__ int   g_rowptr[NN + 1];
__device__ int   g_bsum[64];
__device__ int   g_src[NE];
__device__ float g_nrm[NE];
__device__ __align__(16) float g_h[NN * 128];
__device__ __align__(16) float g_agg[NN * 128];
__device__ float g_pool[NG * 64];
__device__ float g_cnt[NG];

// ---------------- CSR build ----------------
__global__ void k_zero_deg() {
    int i = blockIdx.x * blockDim.x + threadIdx.x;
    if (i < NN) g_deg[i] = 0;
}

__global__ void k_deg_count(const int* __restrict__ ei) {
    int e = blockIdx.x * blockDim.x + threadIdx.x;
    if (e < NE) atomicAdd(&g_deg[ei[NE + e]], 1);
}

// stage 1: per-block inclusive scan of 1024 degrees; also dinv + cursor init
__global__ void k_scan1() {
    __shared__ int sh[1024];
    int tid = threadIdx.x;
    int i = blockIdx.x * 1024 + tid;
    int v = (i < NN) ? g_deg[i] : 0;
    if (i < NN) {
        g_dinv[i] = rsqrtf((float)v + 1.0f);  // +1 self-loop
        g_cur[i] = 0;
    }
    sh[tid] = v;
    __syncthreads();
    for (int off = 1; off < 1024; off <<= 1) {
        int t = (tid >= off) ? sh[tid - off] : 0;
        __syncthreads();
        sh[tid] += t;
        __syncthreads();
    }
    if (i < NN) g_rowptr[i + 1] = sh[tid];
    if (tid == 1023) g_bsum[blockIdx.x] = sh[1023];
}

// stage 2: exclusive scan of block sums (<=64 of them)
__global__ void k_scan2(int nb) {
    __shared__ int sh[64];
    int tid = threadIdx.x;
    int v = (tid < nb) ? g_bsum[tid] : 0;
    sh[tid] = v;
    __syncthreads();
    for (int off = 1; off < 64; off <<= 1) {
        int t = (tid >= off) ? sh[tid - off] : 0;
        __syncthreads();
        sh[tid] += t;
        __syncthreads();
    }
    if (tid < nb) g_bsum[tid] = sh[tid] - v;  // exclusive
    if (tid == 0) g_rowptr[0] = 0;
}

// stage 3: add block offsets
__global__ void k_scan3() {
    int i = blockIdx.x * 1024 + threadIdx.x;
    if (i < NN) g_rowptr[i + 1] += g_bsum[blockIdx.x];
}

__global__ void k_fill(const int* __restrict__ ei) {
    int e = blockIdx.x * blockDim.x + threadIdx.x;
    if (e >= NE) return;
    int r = ei[e];
    int c = ei[NE + e];
    int slot = g_rowptr[c] + atomicAdd(&g_cur[c], 1);
    g_src[slot] = r;
    g_nrm[slot] = g_dinv[r] * g_dinv[c];
}

// ---------------- packed f32x2 helpers ----------------
__device__ __forceinline__ void fma2(unsigned long long& d, unsigned long long a,
                                     unsigned long long b) {
    asm("fma.rn.f32x2 %0, %1, %2, %0;" : "+l"(d) : "l"(a), "l"(b));
}
__device__ __forceinline__ unsigned long long splat2(float a) {
    unsigned long long r;
    asm("mov.b64 %0, {%1, %1};" : "=l"(r) : "f"(a));
    return r;
}
__device__ __forceinline__ float2 unpack2(unsigned long long p) {
    float2 r;
    asm("mov.b64 {%0, %1}, %2;" : "=f"(r.x), "=f"(r.y) : "l"(p));
    return r;
}

// ---------------- GEMM: C[M,BN] = reluOpt(A) @ W, FFMA2 core ----------------
// BM=128, BK=8, 256 threads, per-thread TM=8 x TN (TN/2 packed pairs)
template <int BN, int TN, bool RELU>
__global__ __launch_bounds__(256) void k_gemm(const float* __restrict__ A,
                                              const float* __restrict__ W,
                                              float* __restrict__ C, int M, int K) {
    constexpr int BM = 128, BK = 8, TM = 8, TP = TN / 2;
    __shared__ float As[BK][BM];
    __shared__ __align__(8) float Ws[BK][BN];

    int tid = threadIdx.x;
    int block_row = blockIdx.x * BM;
    constexpr int CG = BN / TN;  // column groups (16)
    int tcol = (tid % CG) * TN;
    int trow = (tid / CG) * TM;

    unsigned long long acc[TM][TP];
#pragma unroll
    for (int i = 0; i < TM; i++)
#pragma unroll
        for (int j = 0; j < TP; j++) acc[i][j] = 0ull;

    for (int k0 = 0; k0 < K; k0 += BK) {
        {
            int m = tid >> 1, seg = tid & 1;
            int gm = block_row + m;
            float4 v = make_float4(0.f, 0.f, 0.f, 0.f);
            if (gm < M) v = *(const float4*)(A + (size_t)gm * K + k0 + seg * 4);
            if (RELU) {
                v.x = fmaxf(v.x, 0.f); v.y = fmaxf(v.y, 0.f);
                v.z = fmaxf(v.z, 0.f); v.w = fmaxf(v.w, 0.f);
            }
            As[seg * 4 + 0][m] = v.x;
            As[seg * 4 + 1][m] = v.y;
            As[seg * 4 + 2][m] = v.z;
            As[seg * 4 + 3][m] = v.w;
        }
        constexpr int WLD = BK * BN / 4;
        if (tid < WLD) {
            int kk = tid / (BN / 4);
            int nn = (tid % (BN / 4)) * 4;
            *(float4*)&Ws[kk][nn] = *(const float4*)(W + (size_t)(k0 + kk) * BN + nn);
        }
        __syncthreads();

#pragma unroll
        for (int kk = 0; kk < BK; kk++) {
            unsigned long long ap[TM], wp[TP];
#pragma unroll
            for (int i = 0; i < TM; i++) ap[i] = splat2(As[kk][trow + i]);
#pragma unroll
            for (int j = 0; j < TP; j++)
                wp[j] = *(const unsigned long long*)&Ws[kk][tcol + 2 * j];
#pragma unroll
            for (int i = 0; i < TM; i++)
#pragma unroll
                for (int j = 0; j < TP; j++) fma2(acc[i][j], ap[i], wp[j]);
        }
        __syncthreads();
    }

#pragma unroll
    for (int i = 0; i < TM; i++) {
        int gm = block_row + trow + i;
        if (gm < M) {
#pragma unroll
            for (int j = 0; j < TP; j += 2) {
                float2 lo = unpack2(acc[i][j]);
                float2 hi = unpack2(acc[i][j + 1]);
                float4 v = make_float4(lo.x, lo.y, hi.x, hi.y);
                *(float4*)(C + (size_t)gm * BN + tcol + 2 * j) = v;
            }
        }
    }
}

// ---------------- gather aggregation: warp per target node ----------------
template <int F>
__global__ void k_gather(const float* __restrict__ b) {
    int warp = (blockIdx.x * blockDim.x + threadIdx.x) >> 5;
    int lane = threadIdx.x & 31;
    if (warp >= NN) return;
    int c = warp;
    float d = g_dinv[c];
    float dd = d * d;

    if (F == 128) {
        float4 v = *((const float4*)(g_h + (size_t)c * 128) + lane);
        float4 bb = *((const float4*)b + lane);
        float4 acc = make_float4(bb.x + dd * v.x, bb.y + dd * v.y,
                                 bb.z + dd * v.z, bb.w + dd * v.w);
        int s0 = g_rowptr[c], s1 = g_rowptr[c + 1];
        for (int j = s0; j < s1; j++) {
            int s = g_src[j];
            float w = g_nrm[j];
            float4 hv = *((const float4*)(g_h + (size_t)s * 128) + lane);
            acc.x = fmaf(w, hv.x, acc.x);
            acc.y = fmaf(w, hv.y, acc.y);
            acc.z = fmaf(w, hv.z, acc.z);
            acc.w = fmaf(w, hv.w, acc.w);
        }
        *((float4*)(g_agg + (size_t)c * 128) + lane) = acc;
    } else {  // F == 64
        float2 v = *((const float2*)(g_h + (size_t)c * 64) + lane);
        float2 bb = *((const float2*)b + lane);
        float2 acc = make_float2(bb.x + dd * v.x, bb.y + dd * v.y);
        int s0 = g_rowptr[c], s1 = g_rowptr[c + 1];
        for (int j = s0; j < s1; j++) {
            int s = g_src[j];
            float w = g_nrm[j];
            float2 hv = *((const float2*)(g_h + (size_t)s * 64) + lane);
            acc.x = fmaf(w, hv.x, acc.x);
            acc.y = fmaf(w, hv.y, acc.y);
        }
        *((float2*)(g_agg + (size_t)c * 64) + lane) = acc;
    }
}

// ---------------- pooling ----------------
__global__ void k_zero_pool() {
    int i = blockIdx.x * blockDim.x + threadIdx.x;
    if (i < NG * 64) g_pool[i] = 0.f;
}

__global__ void k_cnt(const int* __restrict__ batch) {
    int g = threadIdx.x;
    if (g >= NG) return;
    int lo = 0, hi = NN;
    while (lo < hi) { int mid = (lo + hi) >> 1; if (batch[mid] < g) lo = mid + 1; else hi = mid; }
    int a = lo;
    lo = 0; hi = NN;
    while (lo < hi) { int mid = (lo + hi) >> 1; if (batch[mid] < g + 1) lo = mid + 1; else hi = mid; }
    g_cnt[g] = (float)(lo - a);
}

__global__ void k_pool(const int* __restrict__ batch) {
    int f = threadIdx.x;
    int sub = threadIdx.y;
    int chunk = (NN + gridDim.x - 1) / gridDim.x;
    int start = blockIdx.x * chunk;
    int end = min(NN, start + chunk);
    float acc = 0.f;
    int cur = -1;
    for (int i = start + sub; i < end; i += 4) {
        int g = batch[i];
        if (g != cur) {
            if (cur >= 0) atomicAdd(&g_pool[cur * 64 + f], acc);
            cur = g;
            acc = 0.f;
        }
        acc += fmaxf(g_agg[(size_t)i * 64 + f], 0.f);  // relu(h3)
    }
    if (cur >= 0) atomicAdd(&g_pool[cur * 64 + f], acc);
}

// ---------------- FC head ----------------
__global__ void k_fc(const float* __restrict__ Wf1, const float* __restrict__ bf1,
                     const float* __restrict__ Wf2, const float* __restrict__ bf2,
                     float* __restrict__ out) {
    __shared__ float sp[NG * 64];
    __shared__ float sf[NG * 32];
    int tid = threadIdx.x;
    for (int idx = tid; idx < NG * 64; idx += blockDim.x)
        sp[idx] = g_pool[idx] / fmaxf(g_cnt[idx >> 6], 1.0f);
    __syncthreads();
    for (int e = tid; e < NG * 32; e += blockDim.x) {
        int g = e / 32, j = e % 32;
        float s = bf1[j];
#pragma unroll
        for (int k = 0; k < 64; k++) s = fmaf(sp[g * 64 + k], Wf1[k * 32 + j], s);
        sf[e] = fmaxf(s, 0.f);
    }
    __syncthreads();
    for (int e = tid; e < NG * 10; e += blockDim.x) {
        int g = e / 10, j = e % 10;
        float s = bf2[j];
#pragma unroll
        for (int k = 0; k < 32; k++) s = fmaf(sf[g * 32 + k], Wf2[k * 10 + j], s);
        out[e] = s;
    }
}

// ---------------- launch ----------------
extern "C" void kernel_launch(void* const* d_in, const int* in_sizes, int n_in,
                              void* d_out, int out_size) {
    const float* x = (const float*)d_in[0];
    const int* ei = (const int*)d_in[1];
    const int* batch = (const int*)d_in[2];
    const float* W1 = (const float*)d_in[3];
    const float* b1 = (const float*)d_in[4];
    const float* W2 = (const float*)d_in[5];
    const float* b2 = (const float*)d_in[6];
    const float* W3 = (const float*)d_in[7];
    const float* b3 = (const float*)d_in[8];
    const float* Wf1 = (const float*)d_in[9];
    const float* bf1 = (const float*)d_in[10];
    const float* Wf2 = (const float*)d_in[11];
    const float* bf2 = (const float*)d_in[12];
    float* out = (float*)d_out;

    float *p_h = nullptr, *p_agg = nullptr;
    cudaGetSymbolAddress((void**)&p_h, g_h);
    cudaGetSymbolAddress((void**)&p_agg, g_agg);

    const int T = 256;
    int gN = (NN + T - 1) / T;
    int gE = (NE + T - 1) / T;
    int gGemm = (NN + 127) / 128;
    int gGather = (NN * 32 + T - 1) / T;
    int nb = (NN + 1023) / 1024;  // 49

    // CSR build
    k_zero_deg<<<gN, T>>>();
    k_deg_count<<<gE, T>>>(ei);
    k_scan1<<<nb, 1024>>>();
    k_scan2<<<1, 64>>>(nb);
    k_scan3<<<nb, 1024>>>();
    k_fill<<<gE, T>>>(ei);

    // layer 1
    k_gemm<128, 8, false><<<gGemm, T>>>(x, W1, p_h, NN, 128);
    k_gather<128><<<gGather, T>>>(b1);
    // layer 2
    k_gemm<128, 8, true><<<gGemm, T>>>(p_agg, W2, p_h, NN, 128);
    k_gather<128><<<gGather, T>>>(b2);
    // layer 3
    k_gemm<64, 4, true><<<gGemm, T>>>(p_agg, W3, p_h, NN, 128);
    k_gather<64><<<gGather, T>>>(b3);

    // pool + head
    k_zero_pool<<<(NG * 64 + T - 1) / T, T>>>();
    k_cnt<<<1, 64>>>(batch);
    dim3 pb(64, 4);
    k_pool<<<128, pb>>>(batch);
    k_fc<<<1, 256>>>(Wf1, bf1, Wf2, bf2, out);
}

// round 6
// speedup vs baseline: 1.3450x; 1.0863x over previous
#include <cuda_runtime.h>
#include <cuda_bf16.h>

#define NN 50000
#define NE 600000
#define NG 64

// ---- scratch (device globals) ----
__device__ float g_dinv[NN];
__device__ int   g_deg[NN];
__device__ int   g_cur[NN];
__device__ int   g_rowptr[NN + 1];
__device__ int   g_bsum[64];
__device__ int   g_src[NE];
__device__ float g_nrm[NE];
__device__ __align__(16) float g_h[NN * 128];
__device__ __align__(16) float g_agg[NN * 128];
__device__ float g_pool[NG * 64];
__device__ float g_cnt[NG];

// ---------------- CSR build ----------------
__global__ void k_zero_deg() {
    int i = blockIdx.x * blockDim.x + threadIdx.x;
    if (i < NN) g_deg[i] = 0;
}

__global__ void k_deg_count(const int* __restrict__ ei) {
    int e = blockIdx.x * blockDim.x + threadIdx.x;
    if (e < NE) atomicAdd(&g_deg[ei[NE + e]], 1);
}

__global__ void k_scan1() {
    __shared__ int sh[1024];
    int tid = threadIdx.x;
    int i = blockIdx.x * 1024 + tid;
    int v = (i < NN) ? g_deg[i] : 0;
    if (i < NN) {
        g_dinv[i] = rsqrtf((float)v + 1.0f);  // +1 self-loop
        g_cur[i] = 0;
    }
    sh[tid] = v;
    __syncthreads();
    for (int off = 1; off < 1024; off <<= 1) {
        int t = (tid >= off) ? sh[tid - off] : 0;
        __syncthreads();
        sh[tid] += t;
        __syncthreads();
    }
    if (i < NN) g_rowptr[i + 1] = sh[tid];
    if (tid == 1023) g_bsum[blockIdx.x] = sh[1023];
}

__global__ void k_scan2(int nb) {
    __shared__ int sh[64];
    int tid = threadIdx.x;
    int v = (tid < nb) ? g_bsum[tid] : 0;
    sh[tid] = v;
    __syncthreads();
    for (int off = 1; off < 64; off <<= 1) {
        int t = (tid >= off) ? sh[tid - off] : 0;
        __syncthreads();
        sh[tid] += t;
        __syncthreads();
    }
    if (tid < nb) g_bsum[tid] = sh[tid] - v;  // exclusive
    if (tid == 0) g_rowptr[0] = 0;
}

__global__ void k_scan3() {
    int i = blockIdx.x * 1024 + threadIdx.x;
    if (i < NN) g_rowptr[i + 1] += g_bsum[blockIdx.x];
}

__global__ void k_fill(const int* __restrict__ ei) {
    int e = blockIdx.x * blockDim.x + threadIdx.x;
    if (e >= NE) return;
    int r = ei[e];
    int c = ei[NE + e];
    int slot = g_rowptr[c] + atomicAdd(&g_cur[c], 1);
    g_src[slot] = r;
    g_nrm[slot] = g_dinv[r] * g_dinv[c];
}

// ---------------- packed f32x2 helpers ----------------
__device__ __forceinline__ void fma2(unsigned long long& d, unsigned long long a,
                                     unsigned long long b) {
    asm("fma.rn.f32x2 %0, %1, %2, %0;" : "+l"(d) : "l"(a), "l"(b));
}
__device__ __forceinline__ unsigned long long splat2(float a) {
    unsigned long long r;
    asm("mov.b64 %0, {%1, %1};" : "=l"(r) : "f"(a));
    return r;
}
__device__ __forceinline__ unsigned long long pack2(float x, float y) {
    unsigned long long r;
    asm("mov.b64 %0, {%1, %2};" : "=l"(r) : "f"(x), "f"(y));
    return r;
}
__device__ __forceinline__ float2 unpack2(unsigned long long p) {
    float2 r;
    asm("mov.b64 {%0, %1}, %2;" : "=f"(r.x), "=f"(r.y) : "l"(p));
    return r;
}

// ---------------- GEMM: C[M,BN] = reluOpt(A) @ W ----------------
// BM=128, BK=8, 256 threads, per-thread TM=8 rows x TN cols (TP=TN/2 pairs).
// A stored splatted (u64 pairs, broadcast LDS.64), W pairs interleaved [j][group]
// for conflict-free LDS.64. Double-buffered smem, 1 sync per K-step.
template <int BN, int TN, bool RELU>
__global__ __launch_bounds__(256) void k_gemm(const float* __restrict__ A,
                                              const float* __restrict__ W,
                                              float* __restrict__ C, int M, int K) {
    constexpr int BM = 128, BK = 8, TM = 8, TP = TN / 2, CG = BN / TN;
    __shared__ unsigned long long As2[2][BK][BM];        // splatted A pairs
    __shared__ unsigned long long Wp[2][BK][BN / 2];     // [j*CG + g]

    int tid = threadIdx.x;
    int block_row = blockIdx.x * BM;
    int gidx = tid % CG;          // column group
    int trow = (tid / CG) * TM;

    int m = tid >> 1, seg = tid & 1;
    int gm_ld = block_row + m;
    constexpr int WLD = BK * BN / 4;
    int wkk = tid / (BN / 4);
    int wnn = (tid % (BN / 4)) * 4;

    unsigned long long acc[TM][TP];
#pragma unroll
    for (int i = 0; i < TM; i++)
#pragma unroll
        for (int j = 0; j < TP; j++) acc[i][j] = 0ull;

    const int NIT = K / BK;

    // ---- prologue: tile 0 ----
    {
        float4 av = make_float4(0.f, 0.f, 0.f, 0.f);
        if (gm_ld < M) av = *(const float4*)(A + (size_t)gm_ld * K + seg * 4);
        if (RELU) {
            av.x = fmaxf(av.x, 0.f); av.y = fmaxf(av.y, 0.f);
            av.z = fmaxf(av.z, 0.f); av.w = fmaxf(av.w, 0.f);
        }
        As2[0][seg * 4 + 0][m] = splat2(av.x);
        As2[0][seg * 4 + 1][m] = splat2(av.y);
        As2[0][seg * 4 + 2][m] = splat2(av.z);
        As2[0][seg * 4 + 3][m] = splat2(av.w);
        if (tid < WLD) {
            float4 wv = *(const float4*)(W + (size_t)wkk * BN + wnn);
            int pg = wnn >> 1;
            Wp[0][wkk][(pg % TP) * CG + pg / TP] = pack2(wv.x, wv.y);
            Wp[0][wkk][((pg + 1) % TP) * CG + (pg + 1) / TP] = pack2(wv.z, wv.w);
        }
    }
    __syncthreads();

    for (int it = 0; it < NIT; it++) {
        int buf = it & 1;
        float4 av, wv;
        bool has_next = (it + 1 < NIT);
        if (has_next) {
            int k0 = (it + 1) * BK;
            av = make_float4(0.f, 0.f, 0.f, 0.f);
            if (gm_ld < M) av = *(const float4*)(A + (size_t)gm_ld * K + k0 + seg * 4);
            if (tid < WLD) wv = *(const float4*)(W + (size_t)(k0 + wkk) * BN + wnn);
        }

#pragma unroll
        for (int kk = 0; kk < BK; kk++) {
            unsigned long long ap[TM], wp[TP];
#pragma unroll
            for (int i = 0; i < TM; i++) ap[i] = As2[buf][kk][trow + i];
#pragma unroll
            for (int j = 0; j < TP; j++) wp[j] = Wp[buf][kk][j * CG + gidx];
#pragma unroll
            for (int i = 0; i < TM; i++)
#pragma unroll
                for (int j = 0; j < TP; j++) fma2(acc[i][j], ap[i], wp[j]);
        }

        if (has_next) {
            if (RELU) {
                av.x = fmaxf(av.x, 0.f); av.y = fmaxf(av.y, 0.f);
                av.z = fmaxf(av.z, 0.f); av.w = fmaxf(av.w, 0.f);
            }
            int nb = buf ^ 1;
            As2[nb][seg * 4 + 0][m] = splat2(av.x);
            As2[nb][seg * 4 + 1][m] = splat2(av.y);
            As2[nb][seg * 4 + 2][m] = splat2(av.z);
            As2[nb][seg * 4 + 3][m] = splat2(av.w);
            if (tid < WLD) {
                int pg = wnn >> 1;
                Wp[nb][wkk][(pg % TP) * CG + pg / TP] = pack2(wv.x, wv.y);
                Wp[nb][wkk][((pg + 1) % TP) * CG + (pg + 1) / TP] = pack2(wv.z, wv.w);
            }
            __syncthreads();
        }
    }

#pragma unroll
    for (int i = 0; i < TM; i++) {
        int gm = block_row + trow + i;
        if (gm < M) {
#pragma unroll
            for (int j = 0; j < TP; j += 2) {
                float2 lo = unpack2(acc[i][j]);
                float2 hi = unpack2(acc[i][j + 1]);
                float4 v = make_float4(lo.x, lo.y, hi.x, hi.y);
                *(float4*)(C + (size_t)gm * BN + gidx * TN + 2 * j) = v;
            }
        }
    }
}

// ---------------- gather aggregation: warp per target node ----------------
template <int F>
__global__ void k_gather(const float* __restrict__ b) {
    int warp = (blockIdx.x * blockDim.x + threadIdx.x) >> 5;
    int lane = threadIdx.x & 31;
    if (warp >= NN) return;
    int c = warp;
    float d = g_dinv[c];
    float dd = d * d;

    if (F == 128) {
        float4 v = *((const float4*)(g_h + (size_t)c * 128) + lane);
        float4 bb = *((const float4*)b + lane);
        float4 acc = make_float4(bb.x + dd * v.x, bb.y + dd * v.y,
                                 bb.z + dd * v.z, bb.w + dd * v.w);
        int s0 = g_rowptr[c], s1 = g_rowptr[c + 1];
        for (int j = s0; j < s1; j++) {
            int s = g_src[j];
            float w = g_nrm[j];
            float4 hv = *((const float4*)(g_h + (size_t)s * 128) + lane);
            acc.x = fmaf(w, hv.x, acc.x);
            acc.y = fmaf(w, hv.y, acc.y);
            acc.z = fmaf(w, hv.z, acc.z);
            acc.w = fmaf(w, hv.w, acc.w);
        }
        *((float4*)(g_agg + (size_t)c * 128) + lane) = acc;
    } else {  // F == 64
        float2 v = *((const float2*)(g_h + (size_t)c * 64) + lane);
        float2 bb = *((const float2*)b + lane);
        float2 acc = make_float2(bb.x + dd * v.x, bb.y + dd * v.y);
        int s0 = g_rowptr[c], s1 = g_rowptr[c + 1];
        for (int j = s0; j < s1; j++) {
            int s = g_src[j];
            float w = g_nrm[j];
            float2 hv = *((const float2*)(g_h + (size_t)s * 64) + lane);
            acc.x = fmaf(w, hv.x, acc.x);
            acc.y = fmaf(w, hv.y, acc.y);
        }
        *((float2*)(g_agg + (size_t)c * 64) + lane) = acc;
    }
}

// ---------------- pooling ----------------
__global__ void k_zero_pool() {
    int i = blockIdx.x * blockDim.x + threadIdx.x;
    if (i < NG * 64) g_pool[i] = 0.f;
}

__global__ void k_cnt(const int* __restrict__ batch) {
    int g = threadIdx.x;
    if (g >= NG) return;
    int lo = 0, hi = NN;
    while (lo < hi) { int mid = (lo + hi) >> 1; if (batch[mid] < g) lo = mid + 1; else hi = mid; }
    int a = lo;
    lo = 0; hi = NN;
    while (lo < hi) { int mid = (lo + hi) >> 1; if (batch[mid] < g + 1) lo = mid + 1; else hi = mid; }
    g_cnt[g] = (float)(lo - a);
}

__global__ void k_pool(const int* __restrict__ batch) {
    int f = threadIdx.x;
    int sub = threadIdx.y;
    int chunk = (NN + gridDim.x - 1) / gridDim.x;
    int start = blockIdx.x * chunk;
    int end = min(NN, start + chunk);
    float acc = 0.f;
    int cur = -1;
    for (int i = start + sub; i < end; i += 4) {
        int g = batch[i];
        if (g != cur) {
            if (cur >= 0) atomicAdd(&g_pool[cur * 64 + f], acc);
            cur = g;
            acc = 0.f;
        }
        acc += fmaxf(g_agg[(size_t)i * 64 + f], 0.f);  // relu(h3)
    }
    if (cur >= 0) atomicAdd(&g_pool[cur * 64 + f], acc);
}

// ---------------- FC head ----------------
__global__ void k_fc(const float* __restrict__ Wf1, const float* __restrict__ bf1,
                     const float* __restrict__ Wf2, const float* __restrict__ bf2,
                     float* __restrict__ out) {
    __shared__ float sp[NG * 64];
    __shared__ float sf[NG * 32];
    int tid = threadIdx.x;
    for (int idx = tid; idx < NG * 64; idx += blockDim.x)
        sp[idx] = g_pool[idx] / fmaxf(g_cnt[idx >> 6], 1.0f);
    __syncthreads();
    for (int e = tid; e < NG * 32; e += blockDim.x) {
        int g = e / 32, j = e % 32;
        float s = bf1[j];
#pragma unroll
        for (int k = 0; k < 64; k++) s = fmaf(sp[g * 64 + k], Wf1[k * 32 + j], s);
        sf[e] = fmaxf(s, 0.f);
    }
    __syncthreads();
    for (int e = tid; e < NG * 10; e += blockDim.x) {
        int g = e / 10, j = e % 10;
        float s = bf2[j];
#pragma unroll
        for (int k = 0; k < 32; k++) s = fmaf(sf[g * 32 + k], Wf2[k * 10 + j], s);
        out[e] = s;
    }
}

// ---------------- launch ----------------
extern "C" void kernel_launch(void* const* d_in, const int* in_sizes, int n_in,
                              void* d_out, int out_size) {
    const float* x = (const float*)d_in[0];
    const int* ei = (const int*)d_in[1];
    const int* batch = (const int*)d_in[2];
    const float* W1 = (const float*)d_in[3];
    const float* b1 = (const float*)d_in[4];
    const float* W2 = (const float*)d_in[5];
    const float* b2 = (const float*)d_in[6];
    const float* W3 = (const float*)d_in[7];
    const float* b3 = (const float*)d_in[8];
    const float* Wf1 = (const float*)d_in[9];
    const float* bf1 = (const float*)d_in[10];
    const float* Wf2 = (const float*)d_in[11];
    const float* bf2 = (const float*)d_in[12];
    float* out = (float*)d_out;

    float *p_h = nullptr, *p_agg = nullptr;
    cudaGetSymbolAddress((void**)&p_h, g_h);
    cudaGetSymbolAddress((void**)&p_agg, g_agg);

    const int T = 256;
    int gN = (NN + T - 1) / T;
    int gE = (NE + T - 1) / T;
    int gGemm = (NN + 127) / 128;
    int gGather = (NN * 32 + T - 1) / T;
    int nb = (NN + 1023) / 1024;  // 49

    // side stream for the CSR build (fork-join inside graph capture; host-side
    // resource creation only — no device allocation)
    cudaStream_t s2;
    cudaEvent_t evA, evB;
    cudaStreamCreateWithFlags(&s2, cudaStreamNonBlocking);
    cudaEventCreateWithFlags(&evA, cudaEventDisableTiming);
    cudaEventCreateWithFlags(&evB, cudaEventDisableTiming);

    cudaEventRecord(evA, 0);
    cudaStreamWaitEvent(s2, evA, 0);

    // s2: CSR build + pool init + graph counts (independent of GEMM1)
    k_zero_deg<<<gN, T, 0, s2>>>();
    k_deg_count<<<gE, T, 0, s2>>>(ei);
    k_scan1<<<nb, 1024, 0, s2>>>();
    k_scan2<<<1, 64, 0, s2>>>(nb);
    k_scan3<<<nb, 1024, 0, s2>>>();
    k_fill<<<gE, T, 0, s2>>>(ei);
    k_zero_pool<<<(NG * 64 + T - 1) / T, T, 0, s2>>>();
    k_cnt<<<1, 64, 0, s2>>>(batch);
    cudaEventRecord(evB, s2);

    // main stream: GEMM1 runs concurrently with CSR build
    k_gemm<128, 8, false><<<gGemm, T>>>(x, W1, p_h, NN, 128);
    cudaStreamWaitEvent(0, evB, 0);  // join before gather1

    k_gather<128><<<gGather, T>>>(b1);
    k_gemm<128, 8, true><<<gGemm, T>>>(p_agg, W2, p_h, NN, 128);
    k_gather<128><<<gGather, T>>>(b2);
    k_gemm<64, 4, true><<<gGemm, T>>>(p_agg, W3, p_h, NN, 128);
    k_gather<64><<<gGather, T>>>(b3);

    dim3 pb(64, 4);
    k_pool<<<128, pb>>>(batch);
    k_fc<<<1, 256>>>(Wf1, bf1, Wf2, bf2, out);
}

// round 9
// speedup vs baseline: 1.4996x; 1.1149x over previous
#include <cuda_runtime.h>
#include <cuda_fp16.h>

#define NN 50000
#define NE 600000
#define NG 64

// ---- scratch (device globals) ----
__device__ float g_dinv[NN];
__device__ int   g_deg[NN];
__device__ int   g_cur[NN];
__device__ int   g_rowptr[NN + 1];
__device__ int   g_bsum[64];
__device__ int   g_src[NE];
__device__ float g_nrm[NE];
__device__ __align__(16) __half g_hh[NN * 128];   // fp16 hidden states
__device__ __align__(16) float g_agg[NN * 128];
__device__ float g_pool[NG * 64];
__device__ float g_cnt[NG];

// ---------------- CSR build ----------------
__global__ void k_zero_deg() {
    int i = blockIdx.x * blockDim.x + threadIdx.x;
    if (i < NN) g_deg[i] = 0;
}

__global__ void k_deg_count(const int* __restrict__ ei) {
    int e = blockIdx.x * blockDim.x + threadIdx.x;
    if (e < NE) atomicAdd(&g_deg[ei[NE + e]], 1);
}

__global__ void k_scan1() {
    __shared__ int sh[1024];
    int tid = threadIdx.x;
    int i = blockIdx.x * 1024 + tid;
    int v = (i < NN) ? g_deg[i] : 0;
    if (i < NN) {
        g_dinv[i] = rsqrtf((float)v + 1.0f);  // +1 self-loop
        g_cur[i] = 0;
    }
    sh[tid] = v;
    __syncthreads();
    for (int off = 1; off < 1024; off <<= 1) {
        int t = (tid >= off) ? sh[tid - off] : 0;
        __syncthreads();
        sh[tid] += t;
        __syncthreads();
    }
    if (i < NN) g_rowptr[i + 1] = sh[tid];
    if (tid == 1023) g_bsum[blockIdx.x] = sh[1023];
}

__global__ void k_scan2(int nb) {
    __shared__ int sh[64];
    int tid = threadIdx.x;
    int v = (tid < nb) ? g_bsum[tid] : 0;
    sh[tid] = v;
    __syncthreads();
    for (int off = 1; off < 64; off <<= 1) {
        int t = (tid >= off) ? sh[tid - off] : 0;
        __syncthreads();
        sh[tid] += t;
        __syncthreads();
    }
    if (tid < nb) g_bsum[tid] = sh[tid] - v;  // exclusive
    if (tid == 0) g_rowptr[0] = 0;
}

__global__ void k_scan3() {
    int i = blockIdx.x * 1024 + threadIdx.x;
    if (i < NN) g_rowptr[i + 1] += g_bsum[blockIdx.x];
}

__global__ void k_fill(const int* __restrict__ ei) {
    int e = blockIdx.x * blockDim.x + threadIdx.x;
    if (e >= NE) return;
    int r = ei[e];
    int c = ei[NE + e];
    int slot = g_rowptr[c] + atomicAdd(&g_cur[c], 1);
    g_src[slot] = r;
    g_nrm[slot] = g_dinv[r] * g_dinv[c];
}

// ---------------- packed f32x2 helpers ----------------
__device__ __forceinline__ void fma2(unsigned long long& d, unsigned long long a,
                                     unsigned long long b) {
    asm("fma.rn.f32x2 %0, %1, %2, %0;" : "+l"(d) : "l"(a), "l"(b));
}
__device__ __forceinline__ unsigned long long splat2(float a) {
    unsigned long long r;
    asm("mov.b64 %0, {%1, %1};" : "=l"(r) : "f"(a));
    return r;
}
__device__ __forceinline__ unsigned long long pack2(float x, float y) {
    unsigned long long r;
    asm("mov.b64 %0, {%1, %2};" : "=l"(r) : "f"(x), "f"(y));
    return r;
}
__device__ __forceinline__ float2 unpack2(unsigned long long p) {
    float2 r;
    asm("mov.b64 {%0, %1}, %2;" : "=f"(r.x), "=f"(r.y) : "l"(p));
    return r;
}

// ---------------- GEMM: Chalf[M,BN] = reluOpt(A) @ W, FFMA2 core ----------------
// BM=128, BK=8, 256 threads, per-thread TM=8 rows x TN cols (TP=TN/2 pairs).
// Output written as fp16 (feeds the L2-bound gather at half traffic).
template <int BN, int TN, bool RELU>
__global__ __launch_bounds__(256) void k_gemm(const float* __restrict__ A,
                                              const float* __restrict__ W,
                                              __half* __restrict__ C, int M, int K) {
    constexpr int BM = 128, BK = 8, TM = 8, TP = TN / 2, CG = BN / TN;
    __shared__ unsigned long long As2[2][BK][BM];
    __shared__ unsigned long long Wp[2][BK][BN / 2];

    int tid = threadIdx.x;
    int block_row = blockIdx.x * BM;
    int gidx = tid % CG;
    int trow = (tid / CG) * TM;

    int m = tid >> 1, seg = tid & 1;
    int gm_ld = block_row + m;
    constexpr int WLD = BK * BN / 4;
    int wkk = tid / (BN / 4);
    int wnn = (tid % (BN / 4)) * 4;

    unsigned long long acc[TM][TP];
#pragma unroll
    for (int i = 0; i < TM; i++)
#pragma unroll
        for (int j = 0; j < TP; j++) acc[i][j] = 0ull;

    const int NIT = K / BK;

    {
        float4 av = make_float4(0.f, 0.f, 0.f, 0.f);
        if (gm_ld < M) av = *(const float4*)(A + (size_t)gm_ld * K + seg * 4);
        if (RELU) {
            av.x = fmaxf(av.x, 0.f); av.y = fmaxf(av.y, 0.f);
            av.z = fmaxf(av.z, 0.f); av.w = fmaxf(av.w, 0.f);
        }
        As2[0][seg * 4 + 0][m] = splat2(av.x);
        As2[0][seg * 4 + 1][m] = splat2(av.y);
        As2[0][seg * 4 + 2][m] = splat2(av.z);
        As2[0][seg * 4 + 3][m] = splat2(av.w);
        if (tid < WLD) {
            float4 wv = *(const float4*)(W + (size_t)wkk * BN + wnn);
            int pg = wnn >> 1;
            Wp[0][wkk][(pg % TP) * CG + pg / TP] = pack2(wv.x, wv.y);
            Wp[0][wkk][((pg + 1) % TP) * CG + (pg + 1) / TP] = pack2(wv.z, wv.w);
        }
    }
    __syncthreads();

    for (int it = 0; it < NIT; it++) {
        int buf = it & 1;
        float4 av, wv;
        bool has_next = (it + 1 < NIT);
        if (has_next) {
            int k0 = (it + 1) * BK;
            av = make_float4(0.f, 0.f, 0.f, 0.f);
            if (gm_ld < M) av = *(const float4*)(A + (size_t)gm_ld * K + k0 + seg * 4);
            if (tid < WLD) wv = *(const float4*)(W + (size_t)(k0 + wkk) * BN + wnn);
        }

#pragma unroll
        for (int kk = 0; kk < BK; kk++) {
            unsigned long long ap[TM], wp[TP];
#pragma unroll
            for (int i = 0; i < TM; i++) ap[i] = As2[buf][kk][trow + i];
#pragma unroll
            for (int j = 0; j < TP; j++) wp[j] = Wp[buf][kk][j * CG + gidx];
#pragma unroll
            for (int i = 0; i < TM; i++)
#pragma unroll
                for (int j = 0; j < TP; j++) fma2(acc[i][j], ap[i], wp[j]);
        }

        if (has_next) {
            if (RELU) {
                av.x = fmaxf(av.x, 0.f); av.y = fmaxf(av.y, 0.f);
                av.z = fmaxf(av.z, 0.f); av.w = fmaxf(av.w, 0.f);
            }
            int nb = buf ^ 1;
            As2[nb][seg * 4 + 0][m] = splat2(av.x);
            As2[nb][seg * 4 + 1][m] = splat2(av.y);
            As2[nb][seg * 4 + 2][m] = splat2(av.z);
            As2[nb][seg * 4 + 3][m] = splat2(av.w);
            if (tid < WLD) {
                int pg = wnn >> 1;
                Wp[nb][wkk][(pg % TP) * CG + pg / TP] = pack2(wv.x, wv.y);
                Wp[nb][wkk][((pg + 1) % TP) * CG + (pg + 1) / TP] = pack2(wv.z, wv.w);
            }
            __syncthreads();
        }
    }

    // fp16 epilogue
#pragma unroll
    for (int i = 0; i < TM; i++) {
        int gm = block_row + trow + i;
        if (gm < M) {
            __half2 hp[TP];
#pragma unroll
            for (int j = 0; j < TP; j++) {
                float2 f = unpack2(acc[i][j]);
                hp[j] = __float22half2_rn(f);
            }
            __half* cp = C + (size_t)gm * BN + gidx * TN;
            if (TP == 4) {
                uint4 v;
                v.x = *(unsigned*)&hp[0]; v.y = *(unsigned*)&hp[1];
                v.z = *(unsigned*)&hp[2]; v.w = *(unsigned*)&hp[3];
                *(uint4*)cp = v;
            } else {  // TP == 2
                uint2 v;
                v.x = *(unsigned*)&hp[0]; v.y = *(unsigned*)&hp[1];
                *(uint2*)cp = v;
            }
        }
    }
}

// ---------------- gather aggregation: warp per target node, fp16 h ----------------
template <int F>
__global__ void k_gather(const float* __restrict__ b) {
    int warp = (blockIdx.x * blockDim.x + threadIdx.x) >> 5;
    int lane = threadIdx.x & 31;
    if (warp >= NN) return;
    int c = warp;
    float d = g_dinv[c];
    float dd = d * d;

    if (F == 128) {
        // lane covers 4 features: 8 bytes fp16 per edge row
        uint2 u = *((const uint2*)(g_hh + (size_t)c * 128) + lane);
        float2 f0 = __half22float2(*(__half2*)&u.x);
        float2 f1 = __half22float2(*(__half2*)&u.y);
        float4 bb = *((const float4*)b + lane);
        float4 acc = make_float4(bb.x + dd * f0.x, bb.y + dd * f0.y,
                                 bb.z + dd * f1.x, bb.w + dd * f1.y);
        int s0 = g_rowptr[c], s1 = g_rowptr[c + 1];
        for (int j = s0; j < s1; j++) {
            int s = g_src[j];
            float w = g_nrm[j];
            uint2 hu = *((const uint2*)(g_hh + (size_t)s * 128) + lane);
            float2 h0 = __half22float2(*(__half2*)&hu.x);
            float2 h1 = __half22float2(*(__half2*)&hu.y);
            acc.x = fmaf(w, h0.x, acc.x);
            acc.y = fmaf(w, h0.y, acc.y);
            acc.z = fmaf(w, h1.x, acc.z);
            acc.w = fmaf(w, h1.y, acc.w);
        }
        *((float4*)(g_agg + (size_t)c * 128) + lane) = acc;
    } else {  // F == 64: lane covers 2 features (4 bytes/edge)
        unsigned u = *((const unsigned*)(g_hh + (size_t)c * 64) + lane);
        float2 f0 = __half22float2(*(__half2*)&u);
        float2 bb = *((const float2*)b + lane);
        float2 acc = make_float2(bb.x + dd * f0.x, bb.y + dd * f0.y);
        int s0 = g_rowptr[c], s1 = g_rowptr[c + 1];
        for (int j = s0; j < s1; j++) {
            int s = g_src[j];
            float w = g_nrm[j];
            unsigned hu = *((const unsigned*)(g_hh + (size_t)s * 64) + lane);
            float2 h0 = __half22float2(*(__half2*)&hu);
            acc.x = fmaf(w, h0.x, acc.x);
            acc.y = fmaf(w, h0.y, acc.y);
        }
        *((float2*)(g_agg + (size_t)c * 64) + lane) = acc;
    }
}

// ---------------- pooling ----------------
__global__ void k_zero_pool() {
    int i = blockIdx.x * blockDim.x + threadIdx.x;
    if (i < NG * 64) g_pool[i] = 0.f;
}

__global__ void k_cnt(const int* __restrict__ batch) {
    int g = threadIdx.x;
    if (g >= NG) return;
    int lo = 0, hi = NN;
    while (lo < hi) { int mid = (lo + hi) >> 1; if (batch[mid] < g) lo = mid + 1; else hi = mid; }
    int a = lo;
    lo = 0; hi = NN;
    while (lo < hi) { int mid = (lo + hi) >> 1; if (batch[mid] < g + 1) lo = mid + 1; else hi = mid; }
    g_cnt[g] = (float)(lo - a);
}

__global__ void k_pool(const int* __restrict__ batch) {
    int f = threadIdx.x;
    int sub = threadIdx.y;
    int chunk = (NN + gridDim.x - 1) / gridDim.x;
    int start = blockIdx.x * chunk;
    int end = min(NN, start + chunk);
    float acc = 0.f;
    int cur = -1;
    for (int i = start + sub; i < end; i += 4) {
        int g = batch[i];
        if (g != cur) {
            if (cur >= 0) atomicAdd(&g_pool[cur * 64 + f], acc);
            cur = g;
            acc = 0.f;
        }
        acc += fmaxf(g_agg[(size_t)i * 64 + f], 0.f);  // relu(h3)
    }
    if (cur >= 0) atomicAdd(&g_pool[cur * 64 + f], acc);
}

// ---------------- FC head ----------------
__global__ void k_fc(const float* __restrict__ Wf1, const float* __restrict__ bf1,
                     const float* __restrict__ Wf2, const float* __restrict__ bf2,
                     float* __restrict__ out) {
    __shared__ float sp[NG * 64];
    __shared__ float sf[NG * 32];
    int tid = threadIdx.x;
    for (int idx = tid; idx < NG * 64; idx += blockDim.x)
        sp[idx] = g_pool[idx] / fmaxf(g_cnt[idx >> 6], 1.0f);
    __syncthreads();
    for (int e = tid; e < NG * 32; e += blockDim.x) {
        int g = e / 32, j = e % 32;
        float s = bf1[j];
#pragma unroll
        for (int k = 0; k < 64; k++) s = fmaf(sp[g * 64 + k], Wf1[k * 32 + j], s);
        sf[e] = fmaxf(s, 0.f);
    }
    __syncthreads();
    for (int e = tid; e < NG * 10; e += blockDim.x) {
        int g = e / 10, j = e % 10;
        float s = bf2[j];
#pragma unroll
        for (int k = 0; k < 32; k++) s = fmaf(sf[g * 32 + k], Wf2[k * 10 + j], s);
        out[e] = s;
    }
}

// ---------------- launch ----------------
extern "C" void kernel_launch(void* const* d_in, const int* in_sizes, int n_in,
                              void* d_out, int out_size) {
    const float* x = (const float*)d_in[0];
    const int* ei = (const int*)d_in[1];
    const int* batch = (const int*)d_in[2];
    const float* W1 = (const float*)d_in[3];
    const float* b1 = (const float*)d_in[4];
    const float* W2 = (const float*)d_in[5];
    const float* b2 = (const float*)d_in[6];
    const float* W3 = (const float*)d_in[7];
    const float* b3 = (const float*)d_in[8];
    const float* Wf1 = (const float*)d_in[9];
    const float* bf1 = (const float*)d_in[10];
    const float* Wf2 = (const float*)d_in[11];
    const float* bf2 = (const float*)d_in[12];
    float* out = (float*)d_out;

    __half* p_h = nullptr;
    float* p_agg = nullptr;
    cudaGetSymbolAddress((void**)&p_h, g_hh);
    cudaGetSymbolAddress((void**)&p_agg, g_agg);

    const int T = 256;
    int gN = (NN + T - 1) / T;
    int gE = (NE + T - 1) / T;
    int gGemm = (NN + 127) / 128;
    int gGather = (NN * 32 + T - 1) / T;
    int nb = (NN + 1023) / 1024;  // 49

    cudaStream_t s2;
    cudaEvent_t evA, evB;
    cudaStreamCreateWithFlags(&s2, cudaStreamNonBlocking);
    cudaEventCreateWithFlags(&evA, cudaEventDisableTiming);
    cudaEventCreateWithFlags(&evB, cudaEventDisableTiming);

    cudaEventRecord(evA, 0);
    cudaStreamWaitEvent(s2, evA, 0);

    // s2: CSR build + pool init + graph counts (runs under GEMM1)
    k_zero_deg<<<gN, T, 0, s2>>>();
    k_deg_count<<<gE, T, 0, s2>>>(ei);
    k_scan1<<<nb, 1024, 0, s2>>>();
    k_scan2<<<1, 64, 0, s2>>>(nb);
    k_scan3<<<nb, 1024, 0, s2>>>();
    k_fill<<<gE, T, 0, s2>>>(ei);
    k_zero_pool<<<(NG * 64 + T - 1) / T, T, 0, s2>>>();
    k_cnt<<<1, 64, 0, s2>>>(batch);
    cudaEventRecord(evB, s2);

    // main stream
    k_gemm<128, 8, false><<<gGemm, T>>>(x, W1, p_h, NN, 128);
    cudaStreamWaitEvent(0, evB, 0);

    k_gather<128><<<gGather, T>>>(b1);
    k_gemm<128, 8, true><<<gGemm, T>>>(p_agg, W2, p_h, NN, 128);
    k_gather<128><<<gGather, T>>>(b2);
    k_gemm<64, 4, true><<<gGemm, T>>>(p_agg, W3, p_h, NN, 128);
    k_gather<64><<<gGather, T>>>(b3);

    dim3 pb(64, 4);
    k_pool<<<128, pb>>>(batch);
    k_fc<<<1, 256>>>(Wf1, bf1, Wf2, bf2, out);
}